// round 10
// baseline (speedup 1.0000x reference)
#include <cuda_runtime.h>
#include <cuda_bf16.h>
#include <cuda_pipeline.h>

#define NB_ACTIONS 64
#define NB_ELEMS 2080           // 64*65/2
#define EPS 1e-7f
#define WPB 5                   // warps per block (160 threads)

// Whole packed-tril row lives contiguously in smem (2080 floats / warp).
// Pipeline chunks (row-aligned, float4-aligned element offsets):
//   c0: rows [ 0,32)  elems [   0, 528)  132 f4
//   c1: rows [32,48)  elems [ 528,1176)  162 f4
//   c2: rows [48,56)  elems [1176,1596)  105 f4
//   c3: rows [56,64)  elems [1596,2080)  121 f4

// Leftover-pool claim counter (claim index, NOT absolute row) and a
// finished-warp counter used to self-reset state for the next graph replay.
// Both start at 0 (static init) and are returned to 0 by the last warp.
__device__ unsigned int g_claim_ctr;
__device__ unsigned int g_done_ctr;

template<int N4>
__device__ __forceinline__ void pf(float4* __restrict__ dst,
                                   const float4* __restrict__ src, int lane) {
    #pragma unroll
    for (int k = 0; k < N4 / 32; ++k)
        __pipeline_memcpy_async(dst + k * 32 + lane, src + k * 32 + lane, 16);
    if ((N4 & 31) && lane < (N4 & 31))
        __pipeline_memcpy_async(dst + (N4 / 32) * 32 + lane,
                                src + (N4 / 32) * 32 + lane, 16);
}

// y_j += sum_{i in [RB,RE)} d_i * Lraw[i,j]; d broadcast via uniform LDS.128.
// Diagonal accumulated RAW, corrected once per row outside.
template<int RB, int RE>
__device__ __forceinline__ void chunk_mac(const float* __restrict__ s,
                                          const float* __restrict__ sd,
                                          int lane, float& y0, float& y1) {
    int off = RB * (RB + 1) / 2;
    #pragma unroll
    for (int g = RB; g < RE; g += 4) {
        const float4 dv = *(const float4*)(sd + g);
        #pragma unroll
        for (int k = 0; k < 4; ++k) {
            const int i = g + k;
            const float di = (k == 0) ? dv.x : (k == 1) ? dv.y : (k == 2) ? dv.z : dv.w;
            if (i < 32) {
                const float v0 = (lane <= i) ? s[off + lane] : 0.0f;
                y0 = fmaf(di, v0, y0);
            } else {
                y0 = fmaf(di, s[off + lane], y0);     // lane < 32 <= i: always valid
                const float v1 = (lane + 32 <= i) ? s[off + 32 + lane] : 0.0f;
                y1 = fmaf(di, v1, y1);
            }
            off += i + 1;
        }
    }
}

__global__ __launch_bounds__(WPB * 32, 5) void naf_kernel(
    const float* __restrict__ L_flat,
    const float* __restrict__ mu,
    const float* __restrict__ a,
    float* __restrict__ out,
    int batch, int total_warps, int static_iters, int pool_start)
{
    __shared__ __align__(16) float sL[WPB][NB_ELEMS];
    __shared__ __align__(16) float sD[WPB][NB_ACTIONS];

    const int wslot = threadIdx.x >> 5;
    const int lane  = threadIdx.x & 31;
    const int gw    = blockIdx.x * WPB + wslot;

    float* const sw = &sL[wslot][0];
    float4* const b0 = (float4*)(sw);
    float4* const b1 = (float4*)(sw + 528);
    float4* const b2 = (float4*)(sw + 1176);
    float4* const b3 = (float4*)(sw + 1596);
    const float* const sd = &sD[wslot][0];

    int row = gw;                 // first static row (gw < total_warps <= batch)
    int k   = 0;                  // iteration counter

    // ---- prologue: 4 groups = chunks of first row ----
    {
        const float4* src = (const float4*)(L_flat + (size_t)row * NB_ELEMS);
        pf<132>(b0, src,       lane); __pipeline_commit();
        pf<162>(b1, src + 132, lane); __pipeline_commit();
        pf<105>(b2, src + 294, lane); __pipeline_commit();
        pf<121>(b3, src + 399, lane); __pipeline_commit();
    }

    float d0 = a[(size_t)row * NB_ACTIONS + lane]      - mu[(size_t)row * NB_ACTIONS + lane];
    float d1 = a[(size_t)row * NB_ACTIONS + lane + 32] - mu[(size_t)row * NB_ACTIONS + lane + 32];
    sD[wslot][lane]      = d0;
    sD[wslot][lane + 32] = d1;
    __syncwarp();

    while (row < batch) {
        // next row: static stride for the first static_iters rows,
        // then claim leftovers from the shared pool (cold path).
        int nrow;
        if (k + 1 < static_iters) {
            nrow = row + total_warps;
        } else {
            unsigned t = 0;
            if (lane == 0) t = atomicAdd(&g_claim_ctr, 1u);
            t = __shfl_sync(0xffffffffu, t, 0);
            nrow = pool_start + (int)t;
        }
        ++k;
        const bool has_next = (nrow < batch);

        // prefetch next row's d early (4 chunk phases of slack to hide LDG)
        float nd0 = 0.0f, nd1 = 0.0f;
        if (has_next) {
            nd0 = a[(size_t)nrow * NB_ACTIONS + lane]      - mu[(size_t)nrow * NB_ACTIONS + lane];
            nd1 = a[(size_t)nrow * NB_ACTIONS + lane + 32] - mu[(size_t)nrow * NB_ACTIONS + lane + 32];
        }
        const float4* nsrc = has_next
            ? (const float4*)(L_flat + (size_t)nrow * NB_ELEMS) : (const float4*)L_flat;

        float y0 = 0.0f, y1 = 0.0f;
        float r0, r1 = 0.0f;
        const int j1 = lane + 32;

        // chunk 0: rows 0-31
        __pipeline_wait_prior(3); __syncwarp();
        chunk_mac<0, 32>(sw, sd, lane, y0, y1);
        r0 = sw[(lane * (lane + 3)) >> 1];                    // raw diag j=lane
        if (has_next) pf<132>(b0, nsrc, lane);
        __pipeline_commit();

        // chunk 1: rows 32-47
        __pipeline_wait_prior(3); __syncwarp();
        chunk_mac<32, 48>(sw, sd, lane, y0, y1);
        if (lane < 16) r1 = sw[(j1 * (j1 + 3)) >> 1];
        if (has_next) pf<162>(b1, nsrc + 132, lane);
        __pipeline_commit();

        // chunk 2: rows 48-55
        __pipeline_wait_prior(3); __syncwarp();
        chunk_mac<48, 56>(sw, sd, lane, y0, y1);
        if (lane >= 16 && lane < 24) r1 = sw[(j1 * (j1 + 3)) >> 1];
        if (has_next) pf<105>(b2, nsrc + 294, lane);
        __pipeline_commit();

        // chunk 3: rows 56-63
        __pipeline_wait_prior(3); __syncwarp();
        chunk_mac<56, 64>(sw, sd, lane, y0, y1);
        if (lane >= 24) r1 = sw[(j1 * (j1 + 3)) >> 1];
        if (has_next) pf<121>(b3, nsrc + 399, lane);
        __pipeline_commit();

        // diagonal correction: replace raw L_jj by exp(L_jj)+eps in y_j
        y0 = fmaf(d0, (__expf(r0) + EPS) - r0, y0);
        y1 = fmaf(d1, (__expf(r1) + EPS) - r1, y1);

        // quad = sum_j y_j^2 ; warp butterfly reduction
        float q = fmaf(y0, y0, y1 * y1);
        #pragma unroll
        for (int sft = 16; sft > 0; sft >>= 1)
            q += __shfl_xor_sync(0xffffffffu, q, sft);
        if (lane == 0)
            out[row] = -0.5f * q;

        // publish next row's d (all of this row's d reads are done)
        sD[wslot][lane]      = nd0;
        sD[wslot][lane + 32] = nd1;
        __syncwarp();

        d0 = nd0; d1 = nd1;
        row = nrow;
    }

    // ---- self-reset for the next graph replay ----
    // This warp never touches g_claim_ctr again; the LAST warp to finish
    // restores the claim counter to 0 for the next launch.
    if (lane == 0) {
        __threadfence();
        unsigned done = atomicAdd(&g_done_ctr, 1u);
        if (done == (unsigned)total_warps - 1u) {
            atomicExch(&g_claim_ctr, 0u);
            atomicExch(&g_done_ctr, 0u);
        }
    }
}

extern "C" void kernel_launch(void* const* d_in, const int* in_sizes, int n_in,
                              void* d_out, int out_size) {
    const float* L_flat = (const float*)d_in[0];
    const float* mu     = (const float*)d_in[1];
    const float* a      = (const float*)d_in[2];
    float* out          = (float*)d_out;

    const int batch = in_sizes[0] / NB_ELEMS;   // 32768

    // 5 blocks/SM (42.9 KB smem each) x 148 SMs = 740 blocks, 25 warps/SM
    int blocks = 5 * 148;
    const int max_blocks = (batch + WPB - 1) / WPB;
    if (blocks > max_blocks) blocks = max_blocks;
    const int total_warps = blocks * WPB;

    int static_iters = batch / total_warps;     // 8 for batch=32768, 3700 warps
    if (static_iters < 1) static_iters = 1;
    const int pool_start = static_iters * total_warps;

    naf_kernel<<<blocks, WPB * 32>>>(L_flat, mu, a, out,
                                     batch, total_warps, static_iters, pool_start);
}

// round 11
// speedup vs baseline: 1.0110x; 1.0110x over previous
#include <cuda_runtime.h>
#include <cuda_bf16.h>
#include <cuda_pipeline.h>

#define NB_ACTIONS 64
#define NB_ELEMS 2080           // 64*65/2
#define EPS 1e-7f
#define WPB 4                   // warps per block

// Whole packed-tril row lives contiguously in smem (2080 floats / warp).
// Pipeline chunks (row-aligned, float4-aligned element offsets):
//   c0: rows [ 0,32)  elems [   0, 528)  132 f4
//   c1: rows [32,48)  elems [ 528,1176)  162 f4
//   c2: rows [48,56)  elems [1176,1596)  105 f4
//   c3: rows [56,64)  elems [1596,2080)  121 f4

// Leftover-pool claim counter (claim index, NOT absolute row) and a
// finished-warp counter used to self-reset state for the next graph replay.
// Both start at 0 (static init) and are returned to 0 by the last warp.
__device__ unsigned int g_claim_ctr;
__device__ unsigned int g_done_ctr;

template<int N4>
__device__ __forceinline__ void pf(float4* __restrict__ dst,
                                   const float4* __restrict__ src, int lane) {
    #pragma unroll
    for (int k = 0; k < N4 / 32; ++k)
        __pipeline_memcpy_async(dst + k * 32 + lane, src + k * 32 + lane, 16);
    if ((N4 & 31) && lane < (N4 & 31))
        __pipeline_memcpy_async(dst + (N4 / 32) * 32 + lane,
                                src + (N4 / 32) * 32 + lane, 16);
}

// y_j += sum_{i in [RB,RE)} d_i * Lraw[i,j]; d broadcast via uniform LDS.128.
// Diagonal accumulated RAW, corrected once per row outside.
template<int RB, int RE>
__device__ __forceinline__ void chunk_mac(const float* __restrict__ s,
                                          const float* __restrict__ sd,
                                          int lane, float& y0, float& y1) {
    int off = RB * (RB + 1) / 2;
    #pragma unroll
    for (int g = RB; g < RE; g += 4) {
        const float4 dv = *(const float4*)(sd + g);
        #pragma unroll
        for (int k = 0; k < 4; ++k) {
            const int i = g + k;
            const float di = (k == 0) ? dv.x : (k == 1) ? dv.y : (k == 2) ? dv.z : dv.w;
            if (i < 32) {
                const float v0 = (lane <= i) ? s[off + lane] : 0.0f;
                y0 = fmaf(di, v0, y0);
            } else {
                y0 = fmaf(di, s[off + lane], y0);     // lane < 32 <= i: always valid
                const float v1 = (lane + 32 <= i) ? s[off + 32 + lane] : 0.0f;
                y1 = fmaf(di, v1, y1);
            }
            off += i + 1;
        }
    }
}

__global__ __launch_bounds__(WPB * 32, 6) void naf_kernel(
    const float* __restrict__ L_flat,
    const float* __restrict__ mu,
    const float* __restrict__ a,
    float* __restrict__ out,
    int batch, int total_warps, int static_iters, int pool_start)
{
    __shared__ __align__(16) float sL[WPB][NB_ELEMS];
    __shared__ __align__(16) float sD[WPB][NB_ACTIONS];

    const int wslot = threadIdx.x >> 5;
    const int lane  = threadIdx.x & 31;
    const int gw    = blockIdx.x * WPB + wslot;

    float* const sw = &sL[wslot][0];
    float4* const b0 = (float4*)(sw);
    float4* const b1 = (float4*)(sw + 528);
    float4* const b2 = (float4*)(sw + 1176);
    float4* const b3 = (float4*)(sw + 1596);
    const float* const sd = &sD[wslot][0];

    int row = gw;                 // first static row (gw < total_warps <= batch)
    int k   = 0;                  // iteration counter

    // ---- prologue: 4 groups = chunks of first row ----
    {
        const float4* src = (const float4*)(L_flat + (size_t)row * NB_ELEMS);
        pf<132>(b0, src,       lane); __pipeline_commit();
        pf<162>(b1, src + 132, lane); __pipeline_commit();
        pf<105>(b2, src + 294, lane); __pipeline_commit();
        pf<121>(b3, src + 399, lane); __pipeline_commit();
    }

    float d0 = a[(size_t)row * NB_ACTIONS + lane]      - mu[(size_t)row * NB_ACTIONS + lane];
    float d1 = a[(size_t)row * NB_ACTIONS + lane + 32] - mu[(size_t)row * NB_ACTIONS + lane + 32];
    sD[wslot][lane]      = d0;
    sD[wslot][lane + 32] = d1;
    __syncwarp();

    while (row < batch) {
        // next row: static stride for the first static_iters rows,
        // then claim leftovers from the shared pool (cold path).
        int nrow;
        if (k + 1 < static_iters) {
            nrow = row + total_warps;
        } else {
            unsigned t = 0;
            if (lane == 0) t = atomicAdd(&g_claim_ctr, 1u);
            t = __shfl_sync(0xffffffffu, t, 0);
            nrow = pool_start + (int)t;
        }
        ++k;
        const bool has_next = (nrow < batch);

        // prefetch next row's d early (4 chunk phases of slack to hide LDG)
        float nd0 = 0.0f, nd1 = 0.0f;
        if (has_next) {
            nd0 = a[(size_t)nrow * NB_ACTIONS + lane]      - mu[(size_t)nrow * NB_ACTIONS + lane];
            nd1 = a[(size_t)nrow * NB_ACTIONS + lane + 32] - mu[(size_t)nrow * NB_ACTIONS + lane + 32];
        }
        const float4* nsrc = has_next
            ? (const float4*)(L_flat + (size_t)nrow * NB_ELEMS) : (const float4*)L_flat;

        float y0 = 0.0f, y1 = 0.0f;
        float r0, r1 = 0.0f;
        const int j1 = lane + 32;

        // chunk 0: rows 0-31
        __pipeline_wait_prior(3); __syncwarp();
        chunk_mac<0, 32>(sw, sd, lane, y0, y1);
        r0 = sw[(lane * (lane + 3)) >> 1];                    // raw diag j=lane
        if (has_next) pf<132>(b0, nsrc, lane);
        __pipeline_commit();

        // chunk 1: rows 32-47
        __pipeline_wait_prior(3); __syncwarp();
        chunk_mac<32, 48>(sw, sd, lane, y0, y1);
        if (lane < 16) r1 = sw[(j1 * (j1 + 3)) >> 1];
        if (has_next) pf<162>(b1, nsrc + 132, lane);
        __pipeline_commit();

        // chunk 2: rows 48-55
        __pipeline_wait_prior(3); __syncwarp();
        chunk_mac<48, 56>(sw, sd, lane, y0, y1);
        if (lane >= 16 && lane < 24) r1 = sw[(j1 * (j1 + 3)) >> 1];
        if (has_next) pf<105>(b2, nsrc + 294, lane);
        __pipeline_commit();

        // chunk 3: rows 56-63
        __pipeline_wait_prior(3); __syncwarp();
        chunk_mac<56, 64>(sw, sd, lane, y0, y1);
        if (lane >= 24) r1 = sw[(j1 * (j1 + 3)) >> 1];
        if (has_next) pf<121>(b3, nsrc + 399, lane);
        __pipeline_commit();

        // diagonal correction: replace raw L_jj by exp(L_jj)+eps in y_j
        y0 = fmaf(d0, (__expf(r0) + EPS) - r0, y0);
        y1 = fmaf(d1, (__expf(r1) + EPS) - r1, y1);

        // quad = sum_j y_j^2 ; warp butterfly reduction
        float q = fmaf(y0, y0, y1 * y1);
        #pragma unroll
        for (int sft = 16; sft > 0; sft >>= 1)
            q += __shfl_xor_sync(0xffffffffu, q, sft);
        if (lane == 0)
            __stcs(&out[row], -0.5f * q);     // streaming store: write-once output

        // publish next row's d (all of this row's d reads are done)
        sD[wslot][lane]      = nd0;
        sD[wslot][lane + 32] = nd1;
        __syncwarp();

        d0 = nd0; d1 = nd1;
        row = nrow;
    }

    // ---- self-reset for the next graph replay ----
    // Safe without a fence: each warp increments g_done_ctr only after its
    // final g_claim_ctr atomic has completed (same-address L2 atomic order),
    // and the reset fires only after ALL warps have incremented.
    if (lane == 0) {
        unsigned done = atomicAdd(&g_done_ctr, 1u);
        if (done == (unsigned)total_warps - 1u) {
            atomicExch(&g_claim_ctr, 0u);
            atomicExch(&g_done_ctr, 0u);
        }
    }
}

extern "C" void kernel_launch(void* const* d_in, const int* in_sizes, int n_in,
                              void* d_out, int out_size) {
    const float* L_flat = (const float*)d_in[0];
    const float* mu     = (const float*)d_in[1];
    const float* a      = (const float*)d_in[2];
    float* out          = (float*)d_out;

    const int batch = in_sizes[0] / NB_ELEMS;   // 32768

    // 6 blocks/SM (34.3 KB smem each) x 148 SMs = 888 resident, SM-balanced
    int blocks = 6 * 148;
    const int max_blocks = (batch + WPB - 1) / WPB;
    if (blocks > max_blocks) blocks = max_blocks;
    const int total_warps = blocks * WPB;

    int static_iters = batch / total_warps;     // 9 for batch=32768
    if (static_iters < 1) static_iters = 1;
    const int pool_start = static_iters * total_warps;

    naf_kernel<<<blocks, WPB * 32>>>(L_flat, mu, a, out,
                                     batch, total_warps, static_iters, pool_start);
}